// round 9
// baseline (speedup 1.0000x reference)
#include <cuda_runtime.h>
#include <cuda_bf16.h>
#include <math.h>
#include <stdint.h>

#define T_STEPS 1024
#define NBATCH  128
#define NU      512
#define DIN     128
#define EPSF    0.01f
#define SCAN_CTAS 128
#define HSZ     (NBATCH * NU)
#define Z_SMEM (128 * 132 * 4 + 128 * 64 * 4)

// ---------------- device scratch --------------------------------------------
__device__ float g_z[(size_t)T_STEPS * NU * NBATCH];  // [t][j][b]
__device__ float g_h[2 * HSZ];                        // ping-pong h (fp32 state)
__device__ unsigned g_bar_count;
__device__ volatile unsigned g_bar_phase;

// ---------------- fallback grid barrier --------------------------------------
__device__ __forceinline__ void grid_barrier() {
    __syncthreads();
    if (threadIdx.x == 0) {
        unsigned ph = g_bar_phase;
        __threadfence();
        if (atomicAdd(&g_bar_count, 1u) == SCAN_CTAS - 1u) {
            atomicExch(&g_bar_count, 0u);
            __threadfence();
            g_bar_phase = ph + 1u;
        } else {
            while (g_bar_phase == ph) { __nanosleep(32); }
        }
        __threadfence();
    }
    __syncthreads();
}

// ---------------- z precompute: z[t][j][b] -----------------------------------
__global__ void __launch_bounds__(256) z_kernel(const float* __restrict__ x,
                                                const float* __restrict__ Ew,
                                                const float* __restrict__ Eb) {
    extern __shared__ float sm[];
    float* xs = sm;              // [128][132]
    float* ew = sm + 128 * 132;  // [128][64]
    const int t   = blockIdx.x;
    const int tid = threadIdx.x;

    for (int idx = tid; idx < 128 * 32; idx += 256) {
        int b  = idx >> 5;
        int kq = idx & 31;
        float4 v = *(const float4*)(x + ((size_t)b * T_STEPS + t) * DIN + kq * 4);
        *(float4*)(xs + b * 132 + kq * 4) = v;
    }

    const int bg = tid >> 3;
    const int jg = tid & 7;
    const int b0 = bg * 4;
    const int j0 = jg * 8;

    for (int jb = 0; jb < 8; jb++) {
        __syncthreads();
        for (int idx = tid; idx < 128 * 16; idx += 256) {
            int k  = idx >> 4;
            int jq = idx & 15;
            *(float4*)(ew + k * 64 + jq * 4) =
                *(const float4*)(Ew + (size_t)k * NU + jb * 64 + jq * 4);
        }
        __syncthreads();

        float acc[4][8];
        #pragma unroll
        for (int r = 0; r < 4; r++)
            #pragma unroll
            for (int jj = 0; jj < 8; jj++) acc[r][jj] = 0.f;

        #pragma unroll 2
        for (int k = 0; k < 128; k += 4) {
            float4 xv[4];
            #pragma unroll
            for (int r = 0; r < 4; r++)
                xv[r] = *(const float4*)(xs + (b0 + r) * 132 + k);
            #pragma unroll
            for (int kk = 0; kk < 4; kk++) {
                float4 e0 = *(const float4*)(ew + (k + kk) * 64 + j0);
                float4 e1 = *(const float4*)(ew + (k + kk) * 64 + j0 + 4);
                #pragma unroll
                for (int r = 0; r < 4; r++) {
                    float xk = (kk == 0) ? xv[r].x : (kk == 1) ? xv[r].y
                             : (kk == 2) ? xv[r].z : xv[r].w;
                    acc[r][0] += xk * e0.x;  acc[r][1] += xk * e0.y;
                    acc[r][2] += xk * e0.z;  acc[r][3] += xk * e0.w;
                    acc[r][4] += xk * e1.x;  acc[r][5] += xk * e1.y;
                    acc[r][6] += xk * e1.z;  acc[r][7] += xk * e1.w;
                }
            }
        }

        #pragma unroll
        for (int jj = 0; jj < 8; jj++) {
            int j = jb * 64 + j0 + jj;
            float bias = Eb[j];
            float4 v = make_float4(acc[0][jj] + bias, acc[1][jj] + bias,
                                   acc[2][jj] + bias, acc[3][jj] + bias);
            *(float4*)(g_z + ((size_t)t * NU + j) * NBATCH + b0) = v;
        }
    }
}

// ---------------- HMMA scan: 8 clusters x 16 CTAs, 256 threads ---------------
// Same as R8 (passing) except: 3 independent accumulator chains (dHH/dLH/dHL),
// summed after the K loop, to break the 96-deep HMMA RAW chain.
__device__ __forceinline__ void mma16816(float& d0, float& d1, float& d2, float& d3,
                                         unsigned a0, unsigned a1, unsigned a2, unsigned a3,
                                         unsigned b0, unsigned b1) {
    asm volatile(
        "mma.sync.aligned.m16n8k16.row.col.f32.bf16.bf16.f32 "
        "{%0,%1,%2,%3}, {%4,%5,%6,%7}, {%8,%9}, {%0,%1,%2,%3};"
        : "+f"(d0), "+f"(d1), "+f"(d2), "+f"(d3)
        : "r"(a0), "r"(a1), "r"(a2), "r"(a3), "r"(b0), "r"(b1));
}

template <bool CLU>
__global__ void __launch_bounds__(256, 1) scan_kernel(const float* __restrict__ Bm,
                                                      const float* __restrict__ Cm,
                                                      const float* __restrict__ Dw,
                                                      const float* __restrict__ Db,
                                                      float* __restrict__ out) {
    __shared__ float    stgA[32 * 17];       // [j_local][b] A' partials
    __shared__ float    stgW[32 * 17];       // [j_local][b] W partials
    __shared__ unsigned hfH[4096];           // h hi frags  [kt][lane][reg]
    __shared__ unsigned hfL[4096];           // h lo frags

    const int cta  = blockIdx.x;
    const int bb   = cta >> 4;
    const int col0 = (cta & 15) * 32;
    const int tid  = threadIdx.x;
    const int w    = tid >> 5;
    const int lane = tid & 31;

    // ---- build this thread's weight B-fragments (constant over scan) --------
    const int nv  = lane >> 2;          // 0..7 virtual col
    const int mat = nv >> 2;            // 0: A', 1: W
    const int jw  = col0 + w * 4 + (nv & 3);
    unsigned wH[32][2], wL[32][2];
    #pragma unroll
    for (int kt = 0; kt < 32; kt++) {
        #pragma unroll
        for (int r = 0; r < 2; r++) {
            float v[2];
            #pragma unroll
            for (int e = 0; e < 2; e++) {
                int k = kt * 16 + r * 8 + (lane & 3) * 2 + e;
                float d = (k == jw) ? 0.01f : 0.0f;
                v[e] = (mat == 0)
                     ? EPSF * (Bm[(size_t)k * NU + jw] - 0.6f * Bm[(size_t)jw * NU + k] - d)
                     : (Cm[(size_t)k * NU + jw] - 0.6f * Cm[(size_t)jw * NU + k] - d);
            }
            __nv_bfloat162 hi = __float22bfloat162_rn(make_float2(v[0], v[1]));
            float2 hf = make_float2(__low2float(hi), __high2float(hi));
            __nv_bfloat162 lo = __float22bfloat162_rn(make_float2(v[0] - hf.x, v[1] - hf.y));
            wH[kt][r] = *reinterpret_cast<unsigned*>(&hi);
            wL[kt][r] = *reinterpret_cast<unsigned*>(&lo);
        }
    }

    // ---- init: zero h frag tiles (h0 = 0) and prev-h buffer patch -----------
    for (int i = tid; i < 4096; i += 256) { hfH[i] = 0u; hfL[i] = 0u; }
    for (int i = tid; i < 16 * 32; i += 256) {
        int r = i >> 5, c = i & 31;
        g_h[HSZ + (size_t)(bb * 16 + r) * NU + col0 + c] = 0.f;   // buffer 1 (t=0 prev)
    }
    __syncthreads();

    // pointwise ownership: thread -> (b = tid>>4, j0 = (tid&15)*2)
    const int pb  = tid >> 4;
    const int pj0 = (tid & 15) * 2;
    const int pbg = bb * 16 + pb;
    const int pjg = col0 + pj0;

    // D frag coords: m0 = lane>>2, c0 = (lane&3)*2
    const int m0 = lane >> 2;
    const int c0 = (lane & 3) * 2;
    float* stg_d = (c0 < 4) ? stgA : stgW;
    const int jd = w * 4 + (c0 & 3);

    for (int t = 0; t < T_STEPS; t++) {
        // prefetch pointwise operands (overlap with MMA)
        float zv0 = __ldcg(g_z + ((size_t)t * NU + pjg) * NBATCH + pbg);
        float zv1 = __ldcg(g_z + ((size_t)t * NU + pjg + 1) * NBATCH + pbg);
        const float* prv = g_h + (size_t)((t & 1) ^ 1) * HSZ;
        float hold0 = __ldcg(prv + (size_t)pbg * NU + pjg);
        float hold1 = __ldcg(prv + (size_t)pbg * NU + pjg + 1);

        // ---- MMA mainloop: 3 independent accumulator chains -----------------
        float hh0 = 0.f, hh1 = 0.f, hh2 = 0.f, hh3 = 0.f;   // aH * wH
        float lh0 = 0.f, lh1 = 0.f, lh2 = 0.f, lh3 = 0.f;   // aL * wH
        float hl0 = 0.f, hl1 = 0.f, hl2 = 0.f, hl3 = 0.f;   // aH * wL
        #pragma unroll
        for (int kt = 0; kt < 32; kt++) {
            uint4 aH = *(const uint4*)&hfH[(kt * 32 + lane) * 4];
            uint4 aL = *(const uint4*)&hfL[(kt * 32 + lane) * 4];
            mma16816(hh0, hh1, hh2, hh3, aH.x, aH.y, aH.z, aH.w, wH[kt][0], wH[kt][1]);
            mma16816(lh0, lh1, lh2, lh3, aL.x, aL.y, aL.z, aL.w, wH[kt][0], wH[kt][1]);
            mma16816(hl0, hl1, hl2, hl3, aH.x, aH.y, aH.z, aH.w, wL[kt][0], wL[kt][1]);
        }
        float d0 = hh0 + lh0 + hl0;
        float d1 = hh1 + lh1 + hl1;
        float d2 = hh2 + lh2 + hl2;
        float d3 = hh3 + lh3 + hl3;

        // ---- stage D: d0:(m0,c0) d1:(m0,c0+1) d2:(m0+8,c0) d3:(m0+8,c0+1) ---
        stg_d[jd * 17 + m0]           = d0;
        stg_d[(jd + 1) * 17 + m0]     = d1;
        stg_d[jd * 17 + m0 + 8]       = d2;
        stg_d[(jd + 1) * 17 + m0 + 8] = d3;
        __syncthreads();

        // ---- pointwise update ------------------------------------------------
        {
            float da0 = stgA[pj0 * 17 + pb];
            float dw0 = stgW[pj0 * 17 + pb];
            float da1 = stgA[(pj0 + 1) * 17 + pb];
            float dw1 = stgW[(pj0 + 1) * 17 + pb];
            float hn0 = hold0 + da0 + EPSF * tanhf(dw0 + zv0);
            float hn1 = hold1 + da1 + EPSF * tanhf(dw1 + zv1);
            float* dst = g_h + (size_t)(t & 1) * HSZ;
            *(float2*)(dst + (size_t)pbg * NU + pjg) = make_float2(hn0, hn1);
        }

        if (CLU) {
            asm volatile("barrier.cluster.arrive.aligned;" ::: "memory");
            asm volatile("barrier.cluster.wait.aligned;" ::: "memory");
        } else {
            grid_barrier();
        }

        // ---- rebuild h A-fragment tiles from cluster-updated h --------------
        if (t < T_STEPS - 1) {
            const float* src = g_h + (size_t)(t & 1) * HSZ;
            #pragma unroll
            for (int it = 0; it < 16; it++) {
                int wd = it * 256 + tid;
                int kt = wd >> 7;
                int ln = (wd >> 2) & 31;
                int r  = wd & 3;
                int m  = (ln >> 2) + 8 * (r & 1);
                int k  = kt * 16 + (ln & 3) * 2 + 8 * (r >> 1);
                float2 hv = __ldcg((const float2*)(src + (size_t)(bb * 16 + m) * NU + k));
                __nv_bfloat162 hi = __float22bfloat162_rn(hv);
                __nv_bfloat162 lo = __float22bfloat162_rn(
                    make_float2(hv.x - __low2float(hi), hv.y - __high2float(hi)));
                hfH[wd] = *reinterpret_cast<unsigned*>(&hi);
                hfL[wd] = *reinterpret_cast<unsigned*>(&lo);
            }
        }
        __syncthreads();
    }

    // ---------------- epilogue: out[b] = h_final[b] @ Dw + Db ----------------
    {
        const int b = cta;
        const float* hf = g_h + HSZ + (size_t)b * NU;   // (T-1)&1 == 1
        float part[10];
        #pragma unroll
        for (int c = 0; c < 10; c++) part[c] = 0.f;
        for (int k = tid; k < NU; k += 256) {
            float hv = __ldcg(hf + k);
            #pragma unroll
            for (int c = 0; c < 10; c++) part[c] += hv * Dw[k * 10 + c];
        }
        __syncthreads();
        float* red = (float*)hfH;   // reuse frag region (16KB)
        #pragma unroll
        for (int c = 0; c < 10; c++) red[c * 256 + tid] = part[c];
        __syncthreads();
        if (tid < 10) {
            float s = Db[tid];
            for (int i = 0; i < 256; i++) s += red[tid * 256 + i];
            out[b * 10 + tid] = s;
        }
    }
}

// ---------------- launch ------------------------------------------------------
extern "C" void kernel_launch(void* const* d_in, const int* in_sizes, int n_in,
                              void* d_out, int out_size) {
    const float* x  = (const float*)d_in[0];
    const float* B  = (const float*)d_in[1];
    const float* C  = (const float*)d_in[2];
    const float* Ew = (const float*)d_in[3];
    const float* Eb = (const float*)d_in[4];
    const float* Dw = (const float*)d_in[5];
    const float* Db = (const float*)d_in[6];
    float* outp = (float*)d_out;

    cudaFuncSetAttribute(z_kernel, cudaFuncAttributeMaxDynamicSharedMemorySize, Z_SMEM);
    cudaFuncSetAttribute(scan_kernel<true>, cudaFuncAttributeNonPortableClusterSizeAllowed, 1);

    z_kernel<<<T_STEPS, 256, Z_SMEM>>>(x, Ew, Eb);

    cudaLaunchConfig_t cfg = {};
    cfg.gridDim  = dim3(SCAN_CTAS, 1, 1);
    cfg.blockDim = dim3(256, 1, 1);
    cfg.dynamicSmemBytes = 0;
    cfg.stream = 0;
    cudaLaunchAttribute at[1];
    at[0].id = cudaLaunchAttributeClusterDimension;
    at[0].val.clusterDim.x = 16;
    at[0].val.clusterDim.y = 1;
    at[0].val.clusterDim.z = 1;
    cfg.attrs = at;
    cfg.numAttrs = 1;

    int ncl = 0;
    cudaError_t qe = cudaOccupancyMaxActiveClusters(&ncl, scan_kernel<true>, &cfg);
    if (qe == cudaSuccess && ncl >= 1) {
        cudaLaunchKernelEx(&cfg, scan_kernel<true>, B, C, Dw, Db, outp);
    } else {
        cudaGetLastError();
        scan_kernel<false><<<SCAN_CTAS, 256>>>(B, C, Dw, Db, outp);
    }
}

// round 10
// speedup vs baseline: 1.2095x; 1.2095x over previous
#include <cuda_runtime.h>
#include <cuda_bf16.h>
#include <math.h>
#include <stdint.h>

#define T_STEPS 1024
#define NBATCH  128
#define NU      512
#define DIN     128
#define EPSF    0.01f
#define SCAN_CTAS 128
#define HSZ     (NBATCH * NU)
#define Z_SMEM (128 * 132 * 4 + 128 * 64 * 4)

// ---------------- device scratch --------------------------------------------
__device__ float g_z[(size_t)T_STEPS * NU * NBATCH];  // [t][j][b]
__device__ float g_h[2 * HSZ];                        // fp32 h (epilogue only)
__device__ uint2 g_hf[2][8][4096];                    // frag exchange [parity][bb][wd]
__device__ unsigned g_bar_count;
__device__ volatile unsigned g_bar_phase;

// ---------------- fallback grid barrier --------------------------------------
__device__ __forceinline__ void grid_barrier() {
    __syncthreads();
    if (threadIdx.x == 0) {
        unsigned ph = g_bar_phase;
        __threadfence();
        if (atomicAdd(&g_bar_count, 1u) == SCAN_CTAS - 1u) {
            atomicExch(&g_bar_count, 0u);
            __threadfence();
            g_bar_phase = ph + 1u;
        } else {
            while (g_bar_phase == ph) { __nanosleep(32); }
        }
        __threadfence();
    }
    __syncthreads();
}

// ---------------- z precompute: z[t][j][b] -----------------------------------
__global__ void __launch_bounds__(256) z_kernel(const float* __restrict__ x,
                                                const float* __restrict__ Ew,
                                                const float* __restrict__ Eb) {
    extern __shared__ float sm[];
    float* xs = sm;              // [128][132]
    float* ew = sm + 128 * 132;  // [128][64]
    const int t   = blockIdx.x;
    const int tid = threadIdx.x;

    for (int idx = tid; idx < 128 * 32; idx += 256) {
        int b  = idx >> 5;
        int kq = idx & 31;
        float4 v = *(const float4*)(x + ((size_t)b * T_STEPS + t) * DIN + kq * 4);
        *(float4*)(xs + b * 132 + kq * 4) = v;
    }

    const int bg = tid >> 3;
    const int jg = tid & 7;
    const int b0 = bg * 4;
    const int j0 = jg * 8;

    for (int jb = 0; jb < 8; jb++) {
        __syncthreads();
        for (int idx = tid; idx < 128 * 16; idx += 256) {
            int k  = idx >> 4;
            int jq = idx & 15;
            *(float4*)(ew + k * 64 + jq * 4) =
                *(const float4*)(Ew + (size_t)k * NU + jb * 64 + jq * 4);
        }
        __syncthreads();

        float acc[4][8];
        #pragma unroll
        for (int r = 0; r < 4; r++)
            #pragma unroll
            for (int jj = 0; jj < 8; jj++) acc[r][jj] = 0.f;

        #pragma unroll 2
        for (int k = 0; k < 128; k += 4) {
            float4 xv[4];
            #pragma unroll
            for (int r = 0; r < 4; r++)
                xv[r] = *(const float4*)(xs + (b0 + r) * 132 + k);
            #pragma unroll
            for (int kk = 0; kk < 4; kk++) {
                float4 e0 = *(const float4*)(ew + (k + kk) * 64 + j0);
                float4 e1 = *(const float4*)(ew + (k + kk) * 64 + j0 + 4);
                #pragma unroll
                for (int r = 0; r < 4; r++) {
                    float xk = (kk == 0) ? xv[r].x : (kk == 1) ? xv[r].y
                             : (kk == 2) ? xv[r].z : xv[r].w;
                    acc[r][0] += xk * e0.x;  acc[r][1] += xk * e0.y;
                    acc[r][2] += xk * e0.z;  acc[r][3] += xk * e0.w;
                    acc[r][4] += xk * e1.x;  acc[r][5] += xk * e1.y;
                    acc[r][6] += xk * e1.z;  acc[r][7] += xk * e1.w;
                }
            }
        }

        #pragma unroll
        for (int jj = 0; jj < 8; jj++) {
            int j = jb * 64 + j0 + jj;
            float bias = Eb[j];
            float4 v = make_float4(acc[0][jj] + bias, acc[1][jj] + bias,
                                   acc[2][jj] + bias, acc[3][jj] + bias);
            *(float4*)(g_z + ((size_t)t * NU + j) * NBATCH + b0) = v;
        }
    }
}

// ---------------- HMMA scan: 8 clusters x 16 CTAs, 256 threads ---------------
// Same as R8 (passing) except:
//  - h exchanged as PRE-CONVERTED bf16 hi/lo frag words (uint2) via g_hf
//  - hold carried in registers (thread owns same (b, j) pair every step)
//  - fp32 h written only at t = T-1 (epilogue input)
__device__ __forceinline__ void mma16816(float& d0, float& d1, float& d2, float& d3,
                                         unsigned a0, unsigned a1, unsigned a2, unsigned a3,
                                         unsigned b0, unsigned b1) {
    asm volatile(
        "mma.sync.aligned.m16n8k16.row.col.f32.bf16.bf16.f32 "
        "{%0,%1,%2,%3}, {%4,%5,%6,%7}, {%8,%9}, {%0,%1,%2,%3};"
        : "+f"(d0), "+f"(d1), "+f"(d2), "+f"(d3)
        : "r"(a0), "r"(a1), "r"(a2), "r"(a3), "r"(b0), "r"(b1));
}

template <bool CLU>
__global__ void __launch_bounds__(256, 1) scan_kernel(const float* __restrict__ Bm,
                                                      const float* __restrict__ Cm,
                                                      const float* __restrict__ Dw,
                                                      const float* __restrict__ Db,
                                                      float* __restrict__ out) {
    __shared__ float    stgA[32 * 17];       // [j_local][b] A' partials
    __shared__ float    stgW[32 * 17];       // [j_local][b] W partials
    __shared__ unsigned hfH[4096];           // h hi frags  [kt][lane][reg]
    __shared__ unsigned hfL[4096];           // h lo frags

    const int cta  = blockIdx.x;
    const int bb   = cta >> 4;
    const int col0 = (cta & 15) * 32;
    const int tid  = threadIdx.x;
    const int w    = tid >> 5;
    const int lane = tid & 31;

    // ---- build this thread's weight B-fragments (constant over scan) --------
    const int nv  = lane >> 2;          // 0..7 virtual col
    const int mat = nv >> 2;            // 0: A', 1: W
    const int jw  = col0 + w * 4 + (nv & 3);
    unsigned wH[32][2], wL[32][2];
    #pragma unroll
    for (int kt = 0; kt < 32; kt++) {
        #pragma unroll
        for (int r = 0; r < 2; r++) {
            float v[2];
            #pragma unroll
            for (int e = 0; e < 2; e++) {
                int k = kt * 16 + r * 8 + (lane & 3) * 2 + e;
                float d = (k == jw) ? 0.01f : 0.0f;
                v[e] = (mat == 0)
                     ? EPSF * (Bm[(size_t)k * NU + jw] - 0.6f * Bm[(size_t)jw * NU + k] - d)
                     : (Cm[(size_t)k * NU + jw] - 0.6f * Cm[(size_t)jw * NU + k] - d);
            }
            __nv_bfloat162 hi = __float22bfloat162_rn(make_float2(v[0], v[1]));
            float2 hf = make_float2(__low2float(hi), __high2float(hi));
            __nv_bfloat162 lo = __float22bfloat162_rn(make_float2(v[0] - hf.x, v[1] - hf.y));
            wH[kt][r] = *reinterpret_cast<unsigned*>(&hi);
            wL[kt][r] = *reinterpret_cast<unsigned*>(&lo);
        }
    }

    // ---- init: zero h frag tiles (h0 = 0) -----------------------------------
    for (int i = tid; i < 4096; i += 256) { hfH[i] = 0u; hfL[i] = 0u; }
    __syncthreads();

    // pointwise ownership: thread -> (b = tid>>4, j0 = (tid&15)*2)
    const int pb  = tid >> 4;
    const int pj0 = (tid & 15) * 2;
    const int pbg = bb * 16 + pb;
    const int pjg = col0 + pj0;

    // frag word index for this thread's (pb, pjg) pair (inverse of reload map)
    const int wdx = (pjg >> 4) * 128
                  + ((((pb & 7) << 2) | ((pjg >> 1) & 3)) << 2)
                  + ((pb >> 3) | (((pjg >> 3) & 1) << 1));

    // D frag coords: m0 = lane>>2, c0 = (lane&3)*2
    const int m0 = lane >> 2;
    const int c0 = (lane & 3) * 2;
    float* stg_d = (c0 < 4) ? stgA : stgW;
    const int jd = w * 4 + (c0 & 3);

    float hold0 = 0.f, hold1 = 0.f;     // register-carried state (h0 = 0)

    for (int t = 0; t < T_STEPS; t++) {
        // prefetch pointwise operand (overlaps with MMA)
        float zv0 = __ldcg(g_z + ((size_t)t * NU + pjg) * NBATCH + pbg);
        float zv1 = __ldcg(g_z + ((size_t)t * NU + pjg + 1) * NBATCH + pbg);

        // ---- MMA mainloop (single accumulator chain, as R8) -----------------
        float d0 = 0.f, d1 = 0.f, d2 = 0.f, d3 = 0.f;
        #pragma unroll
        for (int kt = 0; kt < 32; kt++) {
            uint4 aH = *(const uint4*)&hfH[(kt * 32 + lane) * 4];
            uint4 aL = *(const uint4*)&hfL[(kt * 32 + lane) * 4];
            mma16816(d0, d1, d2, d3, aH.x, aH.y, aH.z, aH.w, wH[kt][0], wH[kt][1]);
            mma16816(d0, d1, d2, d3, aL.x, aL.y, aL.z, aL.w, wH[kt][0], wH[kt][1]);
            mma16816(d0, d1, d2, d3, aH.x, aH.y, aH.z, aH.w, wL[kt][0], wL[kt][1]);
        }

        // ---- stage D --------------------------------------------------------
        stg_d[jd * 17 + m0]           = d0;
        stg_d[(jd + 1) * 17 + m0]     = d1;
        stg_d[jd * 17 + m0 + 8]       = d2;
        stg_d[(jd + 1) * 17 + m0 + 8] = d3;
        __syncthreads();

        // ---- pointwise update + producer-side frag conversion ---------------
        {
            float da0 = stgA[pj0 * 17 + pb];
            float dw0 = stgW[pj0 * 17 + pb];
            float da1 = stgA[(pj0 + 1) * 17 + pb];
            float dw1 = stgW[(pj0 + 1) * 17 + pb];
            hold0 = hold0 + da0 + EPSF * tanhf(dw0 + zv0);
            hold1 = hold1 + da1 + EPSF * tanhf(dw1 + zv1);
            __nv_bfloat162 hi = __float22bfloat162_rn(make_float2(hold0, hold1));
            __nv_bfloat162 lo = __float22bfloat162_rn(
                make_float2(hold0 - __low2float(hi), hold1 - __high2float(hi)));
            uint2 wv;
            wv.x = *reinterpret_cast<unsigned*>(&hi);
            wv.y = *reinterpret_cast<unsigned*>(&lo);
            g_hf[t & 1][bb][wdx] = wv;
            if (t == T_STEPS - 1) {
                *(float2*)(g_h + HSZ + (size_t)pbg * NU + pjg) = make_float2(hold0, hold1);
            }
        }

        if (CLU) {
            asm volatile("barrier.cluster.arrive.aligned;" ::: "memory");
            asm volatile("barrier.cluster.wait.aligned;" ::: "memory");
        } else {
            grid_barrier();
        }

        // ---- reload frag tiles: pure copy (no conversion) -------------------
        if (t < T_STEPS - 1) {
            const uint2* src = &g_hf[t & 1][bb][0];
            #pragma unroll
            for (int it = 0; it < 16; it++) {
                int wd = it * 256 + tid;
                uint2 v = __ldcg(src + wd);
                hfH[wd] = v.x;
                hfL[wd] = v.y;
            }
        }
        __syncthreads();
    }

    // ---------------- epilogue: out[b] = h_final[b] @ Dw + Db ----------------
    {
        const int b = cta;
        const float* hf = g_h + HSZ + (size_t)b * NU;
        float part[10];
        #pragma unroll
        for (int c = 0; c < 10; c++) part[c] = 0.f;
        for (int k = tid; k < NU; k += 256) {
            float hv = __ldcg(hf + k);
            #pragma unroll
            for (int c = 0; c < 10; c++) part[c] += hv * Dw[k * 10 + c];
        }
        __syncthreads();
        float* red = (float*)hfH;   // reuse frag region (16KB)
        #pragma unroll
        for (int c = 0; c < 10; c++) red[c * 256 + tid] = part[c];
        __syncthreads();
        if (tid < 10) {
            float s = Db[tid];
            for (int i = 0; i < 256; i++) s += red[tid * 256 + i];
            out[b * 10 + tid] = s;
        }
    }
}

// ---------------- launch ------------------------------------------------------
extern "C" void kernel_launch(void* const* d_in, const int* in_sizes, int n_in,
                              void* d_out, int out_size) {
    const float* x  = (const float*)d_in[0];
    const float* B  = (const float*)d_in[1];
    const float* C  = (const float*)d_in[2];
    const float* Ew = (const float*)d_in[3];
    const float* Eb = (const float*)d_in[4];
    const float* Dw = (const float*)d_in[5];
    const float* Db = (const float*)d_in[6];
    float* outp = (float*)d_out;

    cudaFuncSetAttribute(z_kernel, cudaFuncAttributeMaxDynamicSharedMemorySize, Z_SMEM);
    cudaFuncSetAttribute(scan_kernel<true>, cudaFuncAttributeNonPortableClusterSizeAllowed, 1);

    z_kernel<<<T_STEPS, 256, Z_SMEM>>>(x, Ew, Eb);

    cudaLaunchConfig_t cfg = {};
    cfg.gridDim  = dim3(SCAN_CTAS, 1, 1);
    cfg.blockDim = dim3(256, 1, 1);
    cfg.dynamicSmemBytes = 0;
    cfg.stream = 0;
    cudaLaunchAttribute at[1];
    at[0].id = cudaLaunchAttributeClusterDimension;
    at[0].val.clusterDim.x = 16;
    at[0].val.clusterDim.y = 1;
    at[0].val.clusterDim.z = 1;
    cfg.attrs = at;
    cfg.numAttrs = 1;

    int ncl = 0;
    cudaError_t qe = cudaOccupancyMaxActiveClusters(&ncl, scan_kernel<true>, &cfg);
    if (qe == cudaSuccess && ncl >= 1) {
        cudaLaunchKernelEx(&cfg, scan_kernel<true>, B, C, Dw, Db, outp);
    } else {
        cudaGetLastError();
        scan_kernel<false><<<SCAN_CTAS, 256>>>(B, C, Dw, Db, outp);
    }
}